// round 2
// baseline (speedup 1.0000x reference)
#include <cuda_runtime.h>
#include <cstdint>
#include <cstddef>

// Problem constants (fixed shapes for this problem)
#define D          256     // latent dim
#define TM         128     // tokens per block
#define TN         128     // codes per chunk
#define TK         32      // k-step chunk
#define NTHREADS   256

// Dynamic smem: zs[256][128] + 2 x es[32][128]  (floats)
#define ZS_FLOATS  (D * TM)              // 32768
#define ES_FLOATS  (TK * TN)             // 4096
#define SMEM_BYTES ((ZS_FLOATS + 2 * ES_FLOATS) * 4)   // 163840

__device__ float g_enorm[4096];

// ---------------------------------------------------------------------------
// Kernel 1: codebook row norms ||e_k||^2  (one warp per row)
// ---------------------------------------------------------------------------
__global__ void enorm_kernel(const float* __restrict__ e, int K) {
    int row  = blockIdx.x * 8 + (threadIdx.x >> 5);
    int lane = threadIdx.x & 31;
    if (row >= K) return;
    const float4* e4 = (const float4*)(e + (size_t)row * D);
    float4 a = e4[lane];
    float4 b = e4[lane + 32];
    float s = a.x * a.x + a.y * a.y + a.z * a.z + a.w * a.w
            + b.x * b.x + b.y * b.y + b.z * b.z + b.w * b.w;
    #pragma unroll
    for (int off = 16; off; off >>= 1)
        s += __shfl_xor_sync(0xffffffffu, s, off);
    if (lane == 0) g_enorm[row] = s;
}

// ---------------------------------------------------------------------------
// Kernel 2: fused distance-GEMM + argmin + gather
//   Block: 128 tokens x (all 4096 codes, in 128-code chunks), 256 threads,
//   8x8 micro-tile per thread (two float4 frags per dim, quad-spread).
//   z tile fully resident in SMEM (transposed [k][m]); E chunks double-buffered.
// ---------------------------------------------------------------------------
extern __shared__ float smem[];

__global__ void __launch_bounds__(NTHREADS, 1)
vq_kernel(const float* __restrict__ z, const float* __restrict__ emb,
          float* __restrict__ outq, float* __restrict__ outi_f,
          int* __restrict__ outi_i, int K)
{
    float* zs  = smem;                       // [k 0..255][m 0..127]
    float* es0 = smem + ZS_FLOATS;
    float* es1 = es0 + ES_FLOATS;

    const int tid = threadIdx.x;
    const int tx  = tid & 15;
    const int ty  = tid >> 4;
    const int m0  = blockIdx.x * TM;

    const int mA = ty * 4, mB = 64 + ty * 4;   // token frags (ascending)
    const int nA = tx * 4, nB = 64 + tx * 4;   // code  frags (ascending)

    // ---- load z tile transposed into SMEM (conflict-free scalar STS) ----
    #pragma unroll
    for (int i = 0; i < 32; ++i) {
        int idxl = i * NTHREADS + tid;         // 0..8191
        int m  = idxl & 127;
        int kv = idxl >> 7;                    // 0..63 (float4 col)
        float4 v = *(const float4*)(z + (size_t)(m0 + m) * D + kv * 4);
        zs[(kv * 4 + 0) * TM + m] = v.x;
        zs[(kv * 4 + 1) * TM + m] = v.y;
        zs[(kv * 4 + 2) * TM + m] = v.z;
        zs[(kv * 4 + 3) * TM + m] = v.w;
    }

    // ---- prologue: stage E chunk 0 (nc=0, kc=0) ----
    float4 r[4];
    #pragma unroll
    for (int i = 0; i < 4; ++i) {
        int idxl = i * NTHREADS + tid;         // 0..1023
        int n  = idxl & 127;
        int kv = idxl >> 7;                    // 0..7
        r[i] = *(const float4*)(emb + (size_t)n * D + kv * 4);
    }
    #pragma unroll
    for (int i = 0; i < 4; ++i) {
        int idxl = i * NTHREADS + tid;
        int n  = idxl & 127;
        int kv = idxl >> 7;
        es0[(kv * 4 + 0) * TN + n] = r[i].x;
        es0[(kv * 4 + 1) * TN + n] = r[i].y;
        es0[(kv * 4 + 2) * TN + n] = r[i].z;
        es0[(kv * 4 + 3) * TN + n] = r[i].w;
    }
    __syncthreads();

    // running best (distance, index) per owned token row
    float bd[2][4];
    int   bi[2][4];
    #pragma unroll
    for (int im = 0; im < 2; ++im)
        #pragma unroll
        for (int i = 0; i < 4; ++i) { bd[im][i] = 3.402823466e38f; bi[im][i] = 0; }

    const int NCHUNKS = K / TN;                // 32
    int cur = 0;

    for (int nc = 0; nc < NCHUNKS; ++nc) {
        float acc[2][2][4][4];
        #pragma unroll
        for (int a = 0; a < 2; ++a)
            #pragma unroll
            for (int b = 0; b < 2; ++b)
                #pragma unroll
                for (int i = 0; i < 4; ++i)
                    #pragma unroll
                    for (int j = 0; j < 4; ++j) acc[a][b][i][j] = 0.0f;

        #pragma unroll 1
        for (int kc = 0; kc < D / TK; ++kc) {  // 8 k-chunks
            const int t_next = nc * 8 + kc + 1;
            const bool has_next = (t_next < NCHUNKS * 8);

            if (has_next) {
                const int n0t = (t_next >> 3) * TN;
                const int k0t = (t_next & 7) * TK;
                #pragma unroll
                for (int i = 0; i < 4; ++i) {
                    int idxl = i * NTHREADS + tid;
                    int n  = idxl & 127;
                    int kv = idxl >> 7;
                    r[i] = *(const float4*)(emb + (size_t)(n0t + n) * D + k0t + kv * 4);
                }
            }

            const float* esc = cur ? es1 : es0;
            const float* zsc = zs + kc * TK * TM;

            #pragma unroll 8
            for (int kk = 0; kk < TK; ++kk) {
                float4 a0 = *(const float4*)(zsc + kk * TM + mA);
                float4 a1 = *(const float4*)(zsc + kk * TM + mB);
                float4 b0 = *(const float4*)(esc + kk * TN + nA);
                float4 b1 = *(const float4*)(esc + kk * TN + nB);
                float am[2][4] = {{a0.x, a0.y, a0.z, a0.w}, {a1.x, a1.y, a1.z, a1.w}};
                float bn[2][4] = {{b0.x, b0.y, b0.z, b0.w}, {b1.x, b1.y, b1.z, b1.w}};
                #pragma unroll
                for (int im = 0; im < 2; ++im)
                    #pragma unroll
                    for (int i = 0; i < 4; ++i)
                        #pragma unroll
                        for (int in = 0; in < 2; ++in)
                            #pragma unroll
                            for (int j = 0; j < 4; ++j)
                                acc[im][in][i][j] += am[im][i] * bn[in][j];
            }
            __syncthreads();
            if (has_next) {
                float* esd = cur ? es0 : es1;
                #pragma unroll
                for (int i = 0; i < 4; ++i) {
                    int idxl = i * NTHREADS + tid;
                    int n  = idxl & 127;
                    int kv = idxl >> 7;
                    esd[(kv * 4 + 0) * TN + n] = r[i].x;
                    esd[(kv * 4 + 1) * TN + n] = r[i].y;
                    esd[(kv * 4 + 2) * TN + n] = r[i].z;
                    esd[(kv * 4 + 3) * TN + n] = r[i].w;
                }
            }
            __syncthreads();
            cur ^= 1;
        }

        // ---- chunk epilogue: dist = ||e||^2 - 2*dot, running argmin ----
        const int n0 = nc * TN;
        float en[2][4];
        #pragma unroll
        for (int j = 0; j < 4; ++j) {
            en[0][j] = g_enorm[n0 + nA + j];
            en[1][j] = g_enorm[n0 + nB + j];
        }
        #pragma unroll
        for (int im = 0; im < 2; ++im)
            #pragma unroll
            for (int i = 0; i < 4; ++i)
                #pragma unroll
                for (int in = 0; in < 2; ++in)     // ascending n order: nA frags then nB
                    #pragma unroll
                    for (int j = 0; j < 4; ++j) {
                        int   n = n0 + (in ? nB : nA) + j;
                        float d = en[in][j] - 2.0f * acc[im][in][i][j];
                        if (d < bd[im][i]) { bd[im][i] = d; bi[im][i] = n; }  // strict <: keep lowest idx
                    }
    }

    // ---- reduce across the 16 tx lanes sharing each token row ----
    #pragma unroll
    for (int off = 8; off; off >>= 1) {
        #pragma unroll
        for (int im = 0; im < 2; ++im)
            #pragma unroll
            for (int i = 0; i < 4; ++i) {
                float od = __shfl_xor_sync(0xffffffffu, bd[im][i], off);
                int   oi = __shfl_xor_sync(0xffffffffu, bi[im][i], off);
                if (od < bd[im][i] || (od == bd[im][i] && oi < bi[im][i])) {
                    bd[im][i] = od; bi[im][i] = oi;
                }
            }
    }

    __syncthreads();                 // all compute reads of es done; reuse as idx buffer
    int* idx_s = (int*)es0;
    if (tx == 0) {
        #pragma unroll
        for (int i = 0; i < 4; ++i) {
            idx_s[mA + i] = bi[0][i];
            idx_s[mB + i] = bi[1][i];
            if (outi_f) {
                outi_f[m0 + mA + i] = (float)bi[0][i];
                outi_f[m0 + mB + i] = (float)bi[1][i];
            }
            if (outi_i) {
                outi_i[m0 + mA + i] = bi[0][i];
                outi_i[m0 + mB + i] = bi[1][i];
            }
        }
    }
    __syncthreads();

    // ---- gather: z_quantized = embedding[idx]  (64 float4 per row) ----
    if (outq) {
        const float4* emb4  = (const float4*)emb;
        float4*       outq4 = (float4*)outq;
        #pragma unroll 4
        for (int t2 = tid; t2 < TM * (D / 4); t2 += NTHREADS) {
            int row = t2 >> 6;
            int col = t2 & 63;
            int id  = idx_s[row];
            outq4[(size_t)(m0 + row) * (D / 4) + col] = emb4[(size_t)id * (D / 4) + col];
        }
    }
}

// ---------------------------------------------------------------------------
// kernel_launch
// ---------------------------------------------------------------------------
extern "C" void kernel_launch(void* const* d_in, const int* in_sizes, int n_in,
                              void* d_out, int out_size)
{
    const float* z   = (const float*)d_in[0];
    const float* emb = (const float*)d_in[1];
    const int n_tokens = in_sizes[0] / D;   // 65536
    const int K        = in_sizes[1] / D;   // 4096

    // Output layout defense: reference returns (z_quantized, indices).
    float* out    = (float*)d_out;
    float* outq   = nullptr;
    float* outi_f = nullptr;
    int*   outi_i = nullptr;
    const long long full = (long long)n_tokens * D;
    if ((long long)out_size >= full + n_tokens) {
        outq   = out;
        outi_f = out + full;            // indices as float, after quantized block
    } else if ((long long)out_size >= full) {
        outq = out;                     // quantized only
    } else {
        outi_i = (int*)d_out;           // indices only (int32)
    }

    enorm_kernel<<<(K + 7) / 8, 256>>>(emb, K);

    cudaFuncSetAttribute(vq_kernel, cudaFuncAttributeMaxDynamicSharedMemorySize, SMEM_BYTES);
    vq_kernel<<<n_tokens / TM, NTHREADS, SMEM_BYTES>>>(z, emb, outq, outi_f, outi_i, K);
}

// round 4
// speedup vs baseline: 1.0009x; 1.0009x over previous
#include <cuda_runtime.h>
#include <cstdint>
#include <cstddef>

// Problem constants (fixed shapes for this problem)
#define D          256     // latent dim
#define TM         128     // tokens per block
#define TN         128     // codes per chunk
#define TK         32      // k-step chunk
#define NTHREADS   256

// Dynamic smem: zs[256][128] + 2 x es[32][128]  (floats)
#define ZS_FLOATS  (D * TM)              // 32768
#define ES_FLOATS  (TK * TN)             // 4096
#define SMEM_BYTES ((ZS_FLOATS + 2 * ES_FLOATS) * 4)   // 163840

__device__ float g_enorm[4096];

// ---------------------------------------------------------------------------
// Kernel 1: codebook row norms ||e_k||^2  (one warp per row)
// ---------------------------------------------------------------------------
__global__ void enorm_kernel(const float* __restrict__ e, int K) {
    int row  = blockIdx.x * 8 + (threadIdx.x >> 5);
    int lane = threadIdx.x & 31;
    if (row >= K) return;
    const float4* e4 = (const float4*)(e + (size_t)row * D);
    float4 a = e4[lane];
    float4 b = e4[lane + 32];
    float s = a.x * a.x + a.y * a.y + a.z * a.z + a.w * a.w
            + b.x * b.x + b.y * b.y + b.z * b.z + b.w * b.w;
    #pragma unroll
    for (int off = 16; off; off >>= 1)
        s += __shfl_xor_sync(0xffffffffu, s, off);
    if (lane == 0) g_enorm[row] = s;
}

// ---------------------------------------------------------------------------
// Kernel 2: fused distance-GEMM + argmin + gather
//   Block: 128 tokens x (all 4096 codes, in 128-code chunks), 256 threads,
//   8x8 micro-tile per thread (two float4 frags per dim, quad-spread).
//   z tile fully resident in SMEM (transposed [k][m]); E chunks double-buffered.
// ---------------------------------------------------------------------------
extern __shared__ float smem[];

__global__ void __launch_bounds__(NTHREADS, 1)
vq_kernel(const float* __restrict__ z, const float* __restrict__ emb,
          float* __restrict__ outq, float* __restrict__ outi_f,
          int* __restrict__ outi_i, int K)
{
    float* zs  = smem;                       // [k 0..255][m 0..127]
    float* es0 = smem + ZS_FLOATS;
    float* es1 = es0 + ES_FLOATS;

    const int tid = threadIdx.x;
    const int tx  = tid & 15;
    const int ty  = tid >> 4;
    const int m0  = blockIdx.x * TM;

    const int mA = ty * 4, mB = 64 + ty * 4;   // token frags (ascending)
    const int nA = tx * 4, nB = 64 + tx * 4;   // code  frags (ascending)

    // ---- load z tile transposed into SMEM (conflict-free scalar STS) ----
    #pragma unroll
    for (int i = 0; i < 32; ++i) {
        int idxl = i * NTHREADS + tid;         // 0..8191
        int m  = idxl & 127;
        int kv = idxl >> 7;                    // 0..63 (float4 col)
        float4 v = *(const float4*)(z + (size_t)(m0 + m) * D + kv * 4);
        zs[(kv * 4 + 0) * TM + m] = v.x;
        zs[(kv * 4 + 1) * TM + m] = v.y;
        zs[(kv * 4 + 2) * TM + m] = v.z;
        zs[(kv * 4 + 3) * TM + m] = v.w;
    }

    // ---- prologue: stage E chunk 0 (nc=0, kc=0) ----
    float4 r[4];
    #pragma unroll
    for (int i = 0; i < 4; ++i) {
        int idxl = i * NTHREADS + tid;         // 0..1023
        int n  = idxl & 127;
        int kv = idxl >> 7;                    // 0..7
        r[i] = *(const float4*)(emb + (size_t)n * D + kv * 4);
    }
    #pragma unroll
    for (int i = 0; i < 4; ++i) {
        int idxl = i * NTHREADS + tid;
        int n  = idxl & 127;
        int kv = idxl >> 7;
        es0[(kv * 4 + 0) * TN + n] = r[i].x;
        es0[(kv * 4 + 1) * TN + n] = r[i].y;
        es0[(kv * 4 + 2) * TN + n] = r[i].z;
        es0[(kv * 4 + 3) * TN + n] = r[i].w;
    }
    __syncthreads();

    // running best (distance, index) per owned token row
    float bd[2][4];
    int   bi[2][4];
    #pragma unroll
    for (int im = 0; im < 2; ++im)
        #pragma unroll
        for (int i = 0; i < 4; ++i) { bd[im][i] = 3.402823466e38f; bi[im][i] = 0; }

    const int NCHUNKS = K / TN;                // 32
    int cur = 0;

    for (int nc = 0; nc < NCHUNKS; ++nc) {
        float acc[2][2][4][4];
        #pragma unroll
        for (int a = 0; a < 2; ++a)
            #pragma unroll
            for (int b = 0; b < 2; ++b)
                #pragma unroll
                for (int i = 0; i < 4; ++i)
                    #pragma unroll
                    for (int j = 0; j < 4; ++j) acc[a][b][i][j] = 0.0f;

        #pragma unroll 1
        for (int kc = 0; kc < D / TK; ++kc) {  // 8 k-chunks
            const int t_next = nc * 8 + kc + 1;
            const bool has_next = (t_next < NCHUNKS * 8);

            if (has_next) {
                const int n0t = (t_next >> 3) * TN;
                const int k0t = (t_next & 7) * TK;
                #pragma unroll
                for (int i = 0; i < 4; ++i) {
                    int idxl = i * NTHREADS + tid;
                    int n  = idxl & 127;
                    int kv = idxl >> 7;
                    r[i] = *(const float4*)(emb + (size_t)(n0t + n) * D + k0t + kv * 4);
                }
            }

            const float* esc = cur ? es1 : es0;
            const float* zsc = zs + kc * TK * TM;

            #pragma unroll 8
            for (int kk = 0; kk < TK; ++kk) {
                float4 a0 = *(const float4*)(zsc + kk * TM + mA);
                float4 a1 = *(const float4*)(zsc + kk * TM + mB);
                float4 b0 = *(const float4*)(esc + kk * TN + nA);
                float4 b1 = *(const float4*)(esc + kk * TN + nB);
                float am[2][4] = {{a0.x, a0.y, a0.z, a0.w}, {a1.x, a1.y, a1.z, a1.w}};
                float bn[2][4] = {{b0.x, b0.y, b0.z, b0.w}, {b1.x, b1.y, b1.z, b1.w}};
                #pragma unroll
                for (int im = 0; im < 2; ++im)
                    #pragma unroll
                    for (int i = 0; i < 4; ++i)
                        #pragma unroll
                        for (int in = 0; in < 2; ++in)
                            #pragma unroll
                            for (int j = 0; j < 4; ++j)
                                acc[im][in][i][j] += am[im][i] * bn[in][j];
            }
            __syncthreads();
            if (has_next) {
                float* esd = cur ? es0 : es1;
                #pragma unroll
                for (int i = 0; i < 4; ++i) {
                    int idxl = i * NTHREADS + tid;
                    int n  = idxl & 127;
                    int kv = idxl >> 7;
                    esd[(kv * 4 + 0) * TN + n] = r[i].x;
                    esd[(kv * 4 + 1) * TN + n] = r[i].y;
                    esd[(kv * 4 + 2) * TN + n] = r[i].z;
                    esd[(kv * 4 + 3) * TN + n] = r[i].w;
                }
            }
            __syncthreads();
            cur ^= 1;
        }

        // ---- chunk epilogue: dist = ||e||^2 - 2*dot, running argmin ----
        const int n0 = nc * TN;
        float en[2][4];
        #pragma unroll
        for (int j = 0; j < 4; ++j) {
            en[0][j] = g_enorm[n0 + nA + j];
            en[1][j] = g_enorm[n0 + nB + j];
        }
        #pragma unroll
        for (int im = 0; im < 2; ++im)
            #pragma unroll
            for (int i = 0; i < 4; ++i)
                #pragma unroll
                for (int in = 0; in < 2; ++in)     // ascending n order: nA frags then nB
                    #pragma unroll
                    for (int j = 0; j < 4; ++j) {
                        int   n = n0 + (in ? nB : nA) + j;
                        float d = en[in][j] - 2.0f * acc[im][in][i][j];
                        if (d < bd[im][i]) { bd[im][i] = d; bi[im][i] = n; }  // strict <: keep lowest idx
                    }
    }

    // ---- reduce across the 16 tx lanes sharing each token row ----
    #pragma unroll
    for (int off = 8; off; off >>= 1) {
        #pragma unroll
        for (int im = 0; im < 2; ++im)
            #pragma unroll
            for (int i = 0; i < 4; ++i) {
                float od = __shfl_xor_sync(0xffffffffu, bd[im][i], off);
                int   oi = __shfl_xor_sync(0xffffffffu, bi[im][i], off);
                if (od < bd[im][i] || (od == bd[im][i] && oi < bi[im][i])) {
                    bd[im][i] = od; bi[im][i] = oi;
                }
            }
    }

    __syncthreads();                 // all compute reads of es done; reuse as idx buffer
    int* idx_s = (int*)es0;
    if (tx == 0) {
        #pragma unroll
        for (int i = 0; i < 4; ++i) {
            idx_s[mA + i] = bi[0][i];
            idx_s[mB + i] = bi[1][i];
            if (outi_f) {
                outi_f[m0 + mA + i] = (float)bi[0][i];
                outi_f[m0 + mB + i] = (float)bi[1][i];
            }
            if (outi_i) {
                outi_i[m0 + mA + i] = bi[0][i];
                outi_i[m0 + mB + i] = bi[1][i];
            }
        }
    }
    __syncthreads();

    // ---- gather: z_quantized = embedding[idx]  (64 float4 per row) ----
    if (outq) {
        const float4* emb4  = (const float4*)emb;
        float4*       outq4 = (float4*)outq;
        #pragma unroll 4
        for (int t2 = tid; t2 < TM * (D / 4); t2 += NTHREADS) {
            int row = t2 >> 6;
            int col = t2 & 63;
            int id  = idx_s[row];
            outq4[(size_t)(m0 + row) * (D / 4) + col] = emb4[(size_t)id * (D / 4) + col];
        }
    }
}

// ---------------------------------------------------------------------------
// kernel_launch
// ---------------------------------------------------------------------------
extern "C" void kernel_launch(void* const* d_in, const int* in_sizes, int n_in,
                              void* d_out, int out_size)
{
    const float* z   = (const float*)d_in[0];
    const float* emb = (const float*)d_in[1];
    const int n_tokens = in_sizes[0] / D;   // 65536
    const int K        = in_sizes[1] / D;   // 4096

    // Output layout defense: reference returns (z_quantized, indices).
    float* out    = (float*)d_out;
    float* outq   = nullptr;
    float* outi_f = nullptr;
    int*   outi_i = nullptr;
    const long long full = (long long)n_tokens * D;
    if ((long long)out_size >= full + n_tokens) {
        outq   = out;
        outi_f = out + full;            // indices as float, after quantized block
    } else if ((long long)out_size >= full) {
        outq = out;                     // quantized only
    } else {
        outi_i = (int*)d_out;           // indices only (int32)
    }

    enorm_kernel<<<(K + 7) / 8, 256>>>(emb, K);

    cudaFuncSetAttribute(vq_kernel, cudaFuncAttributeMaxDynamicSharedMemorySize, SMEM_BYTES);
    vq_kernel<<<n_tokens / TM, NTHREADS, SMEM_BYTES>>>(z, emb, outq, outi_f, outi_i, K);
}

// round 10
// speedup vs baseline: 2.3811x; 2.3790x over previous
#include <cuda_runtime.h>
#include <cuda_fp16.h>
#include <cstdint>
#include <cstddef>

#define D       256
#define KTOT    512
#define NTOK    65536
#define NCODE   4096
#define THRESH  0.15f

// A: [m][k] rows padded to 520 elems (1040B); B: rows padded to 136 (272B)
#define A_STRIDE_B  1040
#define B_STRIDE_B  272
#define SMEM_A_BYTES (128 * A_STRIDE_B)            // 133120
#define B_BUF_BYTES  (128 * B_STRIDE_B)            // 34816
#define SMEM_B_OFF   SMEM_A_BYTES
#define SMEM_TOTAL   (SMEM_A_BYTES + 2 * B_BUF_BYTES)  // 202752

__device__ __align__(16) __half g_zc[(size_t)NTOK * KTOT];   // [tok][zh(256)|zl(256)]
__device__ __align__(16) __half g_ec[(size_t)NCODE * KTOT];  // [code][eh|el]
__device__ float g_enorm[NCODE];
__device__ int   g_flag_count;
__device__ int   g_flag_list[NTOK];
__device__ unsigned long long g_best[NTOK];   // packed (ordered_dist<<32)|code, flagged only

// ---------------- PTX helpers (base-ISA only) ----------------
__device__ __forceinline__ uint32_t smem_u32(const void* p) {
    uint32_t a;
    asm("{ .reg .u64 t; cvta.to.shared.u64 t, %1; cvt.u32.u64 %0, t; }" : "=r"(a) : "l"(p));
    return a;
}
__device__ __forceinline__ void cp_async16(uint32_t dst, const void* src) {
    asm volatile("cp.async.cg.shared.global [%0], [%1], 16;" :: "r"(dst), "l"(src));
}
#define CP_COMMIT() asm volatile("cp.async.commit_group;" ::: "memory")
#define CP_WAIT(n)  asm volatile("cp.async.wait_group %0;" :: "n"(n) : "memory")

#define LDSM4(r, addr) \
    asm volatile("ldmatrix.sync.aligned.m8n8.x4.shared.b16 {%0,%1,%2,%3}, [%4];" \
        : "=r"((r)[0]), "=r"((r)[1]), "=r"((r)[2]), "=r"((r)[3]) : "r"(addr))

__device__ __forceinline__ void mma16816(float* c, const uint32_t* a, uint32_t b0, uint32_t b1) {
    asm volatile("mma.sync.aligned.m16n8k16.row.col.f32.f16.f16.f32 "
        "{%0,%1,%2,%3}, {%4,%5,%6,%7}, {%8,%9}, {%0,%1,%2,%3};"
        : "+f"(c[0]), "+f"(c[1]), "+f"(c[2]), "+f"(c[3])
        : "r"(a[0]), "r"(a[1]), "r"(a[2]), "r"(a[3]), "r"(b0), "r"(b1));
}

// ---------------- prep kernels ----------------
__global__ void enorm_kernel(const float* __restrict__ e) {
    if (blockIdx.x == 0 && threadIdx.x == 0) g_flag_count = 0;
    int row  = blockIdx.x * 8 + (threadIdx.x >> 5);
    int lane = threadIdx.x & 31;
    if (row >= NCODE) return;
    const float4* e4 = (const float4*)(e + (size_t)row * D);
    float4 a = e4[lane], b = e4[lane + 32];
    float s = a.x*a.x + a.y*a.y + a.z*a.z + a.w*a.w
            + b.x*b.x + b.y*b.y + b.z*b.z + b.w*b.w;
    #pragma unroll
    for (int off = 16; off; off >>= 1) s += __shfl_xor_sync(0xffffffffu, s, off);
    if (lane == 0) g_enorm[row] = s;
}

// hi/lo fp16 split, concatenated along K: dst row = [hi(256) | lo(256)]
// NOTE: [zh|zl].[eh|el] = zh.eh + zl.el; dropped cross terms are O(2^-10)
// relative (fp16 ulp), distance noise sigma ~1.3e-2 -> guarded by THRESH=0.15.
__device__ __forceinline__ void split4cat(float4 v, __half* dst_row, int c4) {
    float f[4] = {v.x, v.y, v.z, v.w};
    ushort h[4], l[4];
    #pragma unroll
    for (int i = 0; i < 4; ++i) {
        __half hb = __float2half(f[i]);
        __half lb = __float2half(f[i] - __half2float(hb));
        h[i] = __half_as_ushort(hb);
        l[i] = __half_as_ushort(lb);
    }
    ushort4 hv = {h[0], h[1], h[2], h[3]};
    ushort4 lv = {l[0], l[1], l[2], l[3]};
    *(ushort4*)((ushort*)dst_row + c4 * 4)       = hv;
    *(ushort4*)((ushort*)dst_row + 256 + c4 * 4) = lv;
}
__global__ void split_z_kernel(const float* __restrict__ z) {
    size_t i = (size_t)blockIdx.x * blockDim.x + threadIdx.x;
    if (i >= (size_t)NTOK * D / 4) return;
    size_t tok = i >> 6; int c4 = (int)(i & 63);
    split4cat(((const float4*)z)[i], g_zc + tok * KTOT, c4);
}
__global__ void split_e_kernel(const float* __restrict__ e) {
    size_t i = (size_t)blockIdx.x * blockDim.x + threadIdx.x;
    if (i >= (size_t)NCODE * D / 4) return;
    size_t code = i >> 6; int c4 = (int)(i & 63);
    split4cat(((const float4*)e)[i], g_ec + code * KTOT, c4);
}

// ---------------- main HMMA kernel ----------------
extern __shared__ __align__(1024) char smem_raw[];

__device__ __forceinline__ void issue_slice(uint32_t sbB, int s, int tid) {
    const int buf = s & 1;
    const int n0  = (s >> 2) * 128;
    const int k0  = (s & 3) * 128;
    #pragma unroll
    for (int it = 0; it < 8; ++it) {
        int i  = it * 256 + tid;            // 0..2047
        int n  = i >> 4;
        int kc = i & 15;
        cp_async16(sbB + buf * B_BUF_BYTES + n * B_STRIDE_B + kc * 16,
                   g_ec + (size_t)(n0 + n) * KTOT + k0 + kc * 8);
    }
    CP_COMMIT();
}

__global__ void __launch_bounds__(256, 1)
vq_main(const float* __restrict__ emb, float* __restrict__ outq,
        float* __restrict__ outi_f, int* __restrict__ outi_i)
{
    const int tid  = threadIdx.x;
    const int wid  = tid >> 5;
    const int lane = tid & 31;
    const int m0   = blockIdx.x * 128;
    const uint32_t sbA = smem_u32(smem_raw);
    const uint32_t sbB = sbA + SMEM_B_OFF;

    const int r0  = (wid & 3) * 32;     // warp_m: 32 token rows
    const int c0w = (wid >> 2) * 64;    // warp_n: 64 code cols

    // ldmatrix lane addressing: j selects which 8x8, rr its row, kk its k-half
    const int j  = lane >> 3;
    const int rr = ((j & 1) * 8 + (lane & 7));
    const int kk = (j >> 1) * 8;

    // ---- stage A (128 x 512 fp16) ----
    #pragma unroll
    for (int it = 0; it < 32; ++it) {
        int i  = it * 256 + tid;            // 0..8191
        int m  = i >> 6;
        int kc = i & 63;
        cp_async16(sbA + m * A_STRIDE_B + kc * 16,
                   g_zc + (size_t)(m0 + m) * KTOT + kc * 8);
    }
    CP_COMMIT();
    issue_slice(sbB, 0, tid);
    issue_slice(sbB, 1, tid);

    float acc[2][8][4];
    float bd[4], b2[4];
    int   bi[4];
    #pragma unroll
    for (int s = 0; s < 4; ++s) { bd[s] = 3.402823466e38f; b2[s] = 3.402823466e38f; bi[s] = 0; }

    for (int s = 0; s < 128; ++s) {
        const int kc = s & 3;
        const int nc = s >> 2;
        // at s>=126 only <=1 group is outstanding: WAIT(1) would be a no-op,
        // so drain fully before reading the final slices.
        if (s >= 126) { CP_WAIT(0); } else { CP_WAIT(1); }
        __syncthreads();

        if (kc == 0) {
            #pragma unroll
            for (int mi = 0; mi < 2; ++mi)
                #pragma unroll
                for (int ni = 0; ni < 8; ++ni)
                    #pragma unroll
                    for (int q = 0; q < 4; ++q) acc[mi][ni][q] = 0.0f;
        }

        const uint32_t aB = sbA + (r0 + rr) * A_STRIDE_B + (kc * 128 + kk) * 2;
        const uint32_t bB = sbB + (s & 1) * B_BUF_BYTES + (c0w + rr) * B_STRIDE_B + kk * 2;

        #pragma unroll
        for (int ks = 0; ks < 8; ++ks) {
            uint32_t a[2][4];
            #pragma unroll
            for (int mi = 0; mi < 2; ++mi)
                LDSM4(a[mi], aB + mi * 16 * A_STRIDE_B + ks * 32);
            #pragma unroll
            for (int nq = 0; nq < 4; ++nq) {
                uint32_t b[4];
                LDSM4(b, bB + nq * 16 * B_STRIDE_B + ks * 32);
                #pragma unroll
                for (int mi = 0; mi < 2; ++mi) {
                    mma16816(acc[mi][nq * 2],     a[mi], b[0], b[2]);
                    mma16816(acc[mi][nq * 2 + 1], a[mi], b[1], b[3]);
                }
            }
        }
        __syncthreads();
        if (s + 2 < 128) issue_slice(sbB, s + 2, tid);

        if (kc == 3) {
            // epilogue for n-chunk nc: d = ||e||^2 - 2*dot, running best/second
            const int cb = nc * 128 + c0w + (lane & 3) * 2;
            float en[16];
            #pragma unroll
            for (int ni = 0; ni < 8; ++ni) {
                en[ni * 2]     = __ldg(g_enorm + cb + ni * 8);
                en[ni * 2 + 1] = __ldg(g_enorm + cb + ni * 8 + 1);
            }
            #pragma unroll
            for (int mi = 0; mi < 2; ++mi)
                #pragma unroll
                for (int hi = 0; hi < 2; ++hi) {
                    const int st = mi * 2 + hi;
                    #pragma unroll
                    for (int ni = 0; ni < 8; ++ni)
                        #pragma unroll
                        for (int p = 0; p < 2; ++p) {
                            float dd = fmaf(acc[mi][ni][hi * 2 + p], -2.0f, en[ni * 2 + p]);
                            int  idx = cb + ni * 8 + p;
                            float od = bd[st];
                            bd[st] = fminf(od, dd);
                            bi[st] = (dd < od) ? idx : bi[st];   // strict <: lowest idx on tie
                            b2[st] = fminf(b2[st], fmaxf(od, dd));
                        }
                }
        }
    }

    // ---- quad reduce (lanes sharing rows differ only in cols) ----
    #pragma unroll
    for (int off = 1; off <= 2; off <<= 1) {
        #pragma unroll
        for (int st = 0; st < 4; ++st) {
            float obd = __shfl_xor_sync(0xffffffffu, bd[st], off);
            float ob2 = __shfl_xor_sync(0xffffffffu, b2[st], off);
            int   obi = __shfl_xor_sync(0xffffffffu, bi[st], off);
            float nb2 = fminf(fminf(b2[st], ob2), fmaxf(bd[st], obd));
            if (obd < bd[st] || (obd == bd[st] && obi < bi[st])) { bd[st] = obd; bi[st] = obi; }
            b2[st] = nb2;
        }
    }

    __syncthreads();   // all cp.async retired (WAIT(0) above); reuse B space
    float* sd   = (float*)(smem_raw + SMEM_B_OFF);
    float* s2   = sd + 256;
    int*   si   = (int*)(s2 + 256);
    int*   idxf = si + 256;

    if ((lane & 3) == 0) {
        const int g = lane >> 2;
        #pragma unroll
        for (int st = 0; st < 4; ++st) {
            int row   = r0 + g + st * 8;
            int wslot = (wid >> 2) * 128 + row;
            sd[wslot] = bd[st]; s2[wslot] = b2[st]; si[wslot] = bi[st];
        }
    }
    __syncthreads();

    if (tid < 128) {
        float d1a = sd[tid], d1b = sd[128 + tid];
        float d2a = s2[tid], d2b = s2[128 + tid];
        int   ia  = si[tid], ib  = si[128 + tid];
        float D2 = fminf(fminf(d2a, d2b), fmaxf(d1a, d1b));
        float D1; int I1;
        if (d1b < d1a || (d1b == d1a && ib < ia)) { D1 = d1b; I1 = ib; }
        else                                      { D1 = d1a; I1 = ia; }
        int token = m0 + tid;
        if (outi_f) outi_f[token] = (float)I1;
        if (outi_i) outi_i[token] = I1;
        if (D2 - D1 < THRESH) {
            int p = atomicAdd(&g_flag_count, 1);
            g_flag_list[p] = token;
            g_best[token]  = 0xFFFFFFFFFFFFFFFFULL;
        }
        idxf[tid] = I1;
    }
    __syncthreads();

    if (outq) {
        const float4* emb4  = (const float4*)emb;
        float4*       outq4 = (float4*)outq;
        #pragma unroll 4
        for (int i = tid; i < 128 * 64; i += 256) {
            int row = i >> 6, c = i & 63;
            outq4[(size_t)(m0 + row) * 64 + c] = emb4[(size_t)idxf[row] * 64 + c];
        }
    }
}

// ---------------- rescue: exact fp32, code-parallel over flagged tokens ----------------
// 512 blocks x 8 warps = 1 warp per code. Flagged z rows staged 16/batch in SMEM.
__global__ void __launch_bounds__(256, 1)
rescue_scan(const float* __restrict__ z, const float* __restrict__ emb)
{
    __shared__ float zt[16][D];
    const int n    = g_flag_count;
    if (n == 0) return;
    const int lane = threadIdx.x & 31;
    const int w    = threadIdx.x >> 5;
    const int code = blockIdx.x * 8 + w;

    const float4* e4 = (const float4*)(emb + (size_t)code * D);
    float4 e0 = e4[lane], e1 = e4[lane + 32];
    float  en = g_enorm[code];

    for (int base = 0; base < n; base += 16) {
        int nb = min(16, n - base);
        __syncthreads();
        for (int i = threadIdx.x; i < nb * 64; i += 256) {
            int ti = i >> 6, c = i & 63;
            ((float4*)zt[ti])[c] =
                ((const float4*)(z + (size_t)g_flag_list[base + ti] * D))[c];
        }
        __syncthreads();
        for (int ti = 0; ti < nb; ++ti) {
            float4 a = ((const float4*)zt[ti])[lane];
            float4 b = ((const float4*)zt[ti])[lane + 32];
            float s = a.x*e0.x + a.y*e0.y + a.z*e0.z + a.w*e0.w
                    + b.x*e1.x + b.y*e1.y + b.z*e1.z + b.w*e1.w;
            #pragma unroll
            for (int off = 16; off; off >>= 1) s += __shfl_xor_sync(0xffffffffu, s, off);
            if (lane == 0) {
                float d = fmaf(s, -2.0f, en);
                unsigned int bits = __float_as_uint(d);
                unsigned int key  = (bits & 0x80000000u) ? ~bits : (bits | 0x80000000u);
                unsigned long long pk = ((unsigned long long)key << 32) | (unsigned)code;
                atomicMin(&g_best[g_flag_list[base + ti]], pk);
            }
        }
    }
}

__global__ void __launch_bounds__(256, 1)
rescue_fix(const float* __restrict__ emb, float* __restrict__ outq,
           float* __restrict__ outi_f, int* __restrict__ outi_i)
{
    const int n = g_flag_count;
    for (int fi = blockIdx.x; fi < n; fi += gridDim.x) {
        const int token = g_flag_list[fi];
        const int best  = (int)(g_best[token] & 0xFFFFFFFFu);
        if (threadIdx.x == 0) {
            if (outi_f) outi_f[token] = (float)best;
            if (outi_i) outi_i[token] = best;
        }
        if (outq) {
            for (int c = threadIdx.x; c < 64; c += 256)
                ((float4*)(outq + (size_t)token * D))[c] =
                    ((const float4*)(emb + (size_t)best * D))[c];
        }
    }
}

// ---------------- kernel_launch ----------------
extern "C" void kernel_launch(void* const* d_in, const int* in_sizes, int n_in,
                              void* d_out, int out_size)
{
    const float* z   = (const float*)d_in[0];
    const float* emb = (const float*)d_in[1];
    const int n_tokens = in_sizes[0] / D;   // 65536

    // Output layout defense: reference returns (z_quantized, indices).
    float* out    = (float*)d_out;
    float* outq   = nullptr;
    float* outi_f = nullptr;
    int*   outi_i = nullptr;
    const long long full = (long long)n_tokens * D;
    if ((long long)out_size >= full + n_tokens) { outq = out; outi_f = out + full; }
    else if ((long long)out_size >= full)       { outq = out; }
    else                                        { outi_i = (int*)d_out; }

    split_z_kernel<<<(NTOK * D / 4 + 255) / 256, 256>>>(z);
    split_e_kernel<<<(NCODE * D / 4 + 255) / 256, 256>>>(emb);
    enorm_kernel<<<NCODE / 8, 256>>>(emb);

    cudaFuncSetAttribute(vq_main, cudaFuncAttributeMaxDynamicSharedMemorySize, SMEM_TOTAL);
    vq_main<<<n_tokens / 128, 256, SMEM_TOTAL>>>(emb, outq, outi_f, outi_i);

    rescue_scan<<<NCODE / 8, 256>>>(z, emb);
    rescue_fix<<<128, 256>>>(emb, outq, outi_f, outi_i);
}

// round 13
// speedup vs baseline: 2.5373x; 1.0656x over previous
#include <cuda_runtime.h>
#include <cuda_fp16.h>
#include <cstdint>
#include <cstddef>
#include <cstring>

#define D       256
#define NTOK    65536
#define NCODE   4096
#define THRESH  0.15f

// A: [m][k] rows 256 fp16 padded to 264 (528B); B: rows 128 fp16 padded to 136 (272B)
#define A_STRIDE_B  528
#define B_STRIDE_B  272
#define SMEM_A_BYTES (128 * A_STRIDE_B)            // 67584
#define B_BUF_BYTES  (128 * B_STRIDE_B)            // 34816
#define SMEM_B_OFF   SMEM_A_BYTES
#define SMEM_TOTAL   (SMEM_A_BYTES + 2 * B_BUF_BYTES)  // 137216

__device__ __align__(16) __half g_zc[(size_t)NTOK * D];    // fp16(z)  32MB
__device__ __align__(16) __half g_ec[(size_t)NCODE * D];   // fp16(e)   2MB
__device__ float g_enorm[NCODE];
__device__ int   g_flag_count;
__device__ int   g_flag_list[NTOK];
__device__ unsigned long long g_best[NTOK];   // packed (ordered_dist<<32)|code, flagged only

// ---------------- PTX helpers (base-ISA only) ----------------
__device__ __forceinline__ uint32_t smem_u32(const void* p) {
    uint32_t a;
    asm("{ .reg .u64 t; cvta.to.shared.u64 t, %1; cvt.u32.u64 %0, t; }" : "=r"(a) : "l"(p));
    return a;
}
__device__ __forceinline__ void cp_async16(uint32_t dst, const void* src) {
    asm volatile("cp.async.cg.shared.global [%0], [%1], 16;" :: "r"(dst), "l"(src));
}
#define CP_COMMIT() asm volatile("cp.async.commit_group;" ::: "memory")
#define CP_WAIT(n)  asm volatile("cp.async.wait_group %0;" :: "n"(n) : "memory")

#define LDSM4(r, addr) \
    asm volatile("ldmatrix.sync.aligned.m8n8.x4.shared.b16 {%0,%1,%2,%3}, [%4];" \
        : "=r"((r)[0]), "=r"((r)[1]), "=r"((r)[2]), "=r"((r)[3]) : "r"(addr))

__device__ __forceinline__ void mma16816(float* c, const uint32_t* a, uint32_t b0, uint32_t b1) {
    asm volatile("mma.sync.aligned.m16n8k16.row.col.f32.f16.f16.f32 "
        "{%0,%1,%2,%3}, {%4,%5,%6,%7}, {%8,%9}, {%0,%1,%2,%3};"
        : "+f"(c[0]), "+f"(c[1]), "+f"(c[2]), "+f"(c[3])
        : "r"(a[0]), "r"(a[1]), "r"(a[2]), "r"(a[3]), "r"(b0), "r"(b1));
}

// ---------------- prep kernels ----------------
__global__ void enorm_kernel(const float* __restrict__ e) {
    if (blockIdx.x == 0 && threadIdx.x == 0) g_flag_count = 0;
    int row  = blockIdx.x * 8 + (threadIdx.x >> 5);
    int lane = threadIdx.x & 31;
    if (row >= NCODE) return;
    const float4* e4 = (const float4*)(e + (size_t)row * D);
    float4 a = e4[lane], b = e4[lane + 32];
    float s = a.x*a.x + a.y*a.y + a.z*a.z + a.w*a.w
            + b.x*b.x + b.y*b.y + b.z*b.z + b.w*b.w;
    #pragma unroll
    for (int off = 16; off; off >>= 1) s += __shfl_xor_sync(0xffffffffu, s, off);
    if (lane == 0) g_enorm[row] = s;
}

// fp32 -> fp16 convert (hi only), writing the __device__ globals from DEVICE
// code (host code cannot take a __device__ symbol's address as a kernel arg).
// Dropped bits are O(2^-11) relative; distance noise sigma ~1.3e-2, guarded
// by THRESH=0.15 + exact-fp32 rescue.
__device__ __forceinline__ void conv4(const float4* src, __half* dst, int i) {
    float4 v = src[i];
    __half2 h0 = __floats2half2_rn(v.x, v.y);
    __half2 h1 = __floats2half2_rn(v.z, v.w);
    uint2 pk;
    memcpy(&pk.x, &h0, 4);
    memcpy(&pk.y, &h1, 4);
    ((uint2*)dst)[i] = pk;
}
__global__ void conv_z_kernel(const float* __restrict__ z) {
    int i = blockIdx.x * blockDim.x + threadIdx.x;
    if (i < NTOK * D / 4) conv4((const float4*)z, g_zc, i);
}
__global__ void conv_e_kernel(const float* __restrict__ e) {
    int i = blockIdx.x * blockDim.x + threadIdx.x;
    if (i < NCODE * D / 4) conv4((const float4*)e, g_ec, i);
}

// ---------------- main HMMA kernel ----------------
extern __shared__ __align__(1024) char smem_raw[];

__device__ __forceinline__ void issue_slice(uint32_t sbB, int s, int tid) {
    const int buf = s & 1;
    const int n0  = (s >> 1) * 128;
    const int k0  = (s & 1) * 128;
    #pragma unroll
    for (int it = 0; it < 8; ++it) {
        int i  = it * 256 + tid;            // 0..2047
        int n  = i >> 4;
        int kc = i & 15;
        cp_async16(sbB + buf * B_BUF_BYTES + n * B_STRIDE_B + kc * 16,
                   g_ec + (size_t)(n0 + n) * D + k0 + kc * 8);
    }
    CP_COMMIT();
}

__global__ void __launch_bounds__(256, 1)
vq_main(const float* __restrict__ emb, float* __restrict__ outq,
        float* __restrict__ outi_f, int* __restrict__ outi_i)
{
    const int tid  = threadIdx.x;
    const int wid  = tid >> 5;
    const int lane = tid & 31;
    const int m0   = blockIdx.x * 128;
    const uint32_t sbA = smem_u32(smem_raw);
    const uint32_t sbB = sbA + SMEM_B_OFF;

    const int r0  = (wid & 3) * 32;     // warp_m: 32 token rows
    const int c0w = (wid >> 2) * 64;    // warp_n: 64 code cols

    // ldmatrix lane addressing: j selects which 8x8, rr its row, kk its k-half
    const int j  = lane >> 3;
    const int rr = ((j & 1) * 8 + (lane & 7));
    const int kk = (j >> 1) * 8;

    // ---- stage A (128 x 256 fp16) ----
    #pragma unroll
    for (int it = 0; it < 16; ++it) {
        int i  = it * 256 + tid;            // 0..4095
        int m  = i >> 5;
        int kc = i & 31;
        cp_async16(sbA + m * A_STRIDE_B + kc * 16,
                   g_zc + (size_t)(m0 + m) * D + kc * 8);
    }
    CP_COMMIT();
    issue_slice(sbB, 0, tid);
    issue_slice(sbB, 1, tid);

    float acc[2][8][4];
    float bd[4], b2[4];
    int   bi[4];
    #pragma unroll
    for (int s = 0; s < 4; ++s) { bd[s] = 3.402823466e38f; b2[s] = 3.402823466e38f; bi[s] = 0; }

    for (int s = 0; s < 64; ++s) {
        const int kc = s & 1;
        const int nc = s >> 1;
        // at s>=62 only <=1 group is outstanding: WAIT(1) would be a no-op,
        // so drain fully before reading the final slices.
        if (s >= 62) { CP_WAIT(0); } else { CP_WAIT(1); }
        __syncthreads();

        if (kc == 0) {
            #pragma unroll
            for (int mi = 0; mi < 2; ++mi)
                #pragma unroll
                for (int ni = 0; ni < 8; ++ni)
                    #pragma unroll
                    for (int q = 0; q < 4; ++q) acc[mi][ni][q] = 0.0f;
        }

        const uint32_t aB = sbA + (r0 + rr) * A_STRIDE_B + (kc * 128 + kk) * 2;
        const uint32_t bB = sbB + (s & 1) * B_BUF_BYTES + (c0w + rr) * B_STRIDE_B + kk * 2;

        #pragma unroll
        for (int ks = 0; ks < 8; ++ks) {
            uint32_t a[2][4];
            #pragma unroll
            for (int mi = 0; mi < 2; ++mi)
                LDSM4(a[mi], aB + mi * 16 * A_STRIDE_B + ks * 32);
            #pragma unroll
            for (int nq = 0; nq < 4; ++nq) {
                uint32_t b[4];
                LDSM4(b, bB + nq * 16 * B_STRIDE_B + ks * 32);
                #pragma unroll
                for (int mi = 0; mi < 2; ++mi) {
                    mma16816(acc[mi][nq * 2],     a[mi], b[0], b[2]);
                    mma16816(acc[mi][nq * 2 + 1], a[mi], b[1], b[3]);
                }
            }
        }
        __syncthreads();
        if (s + 2 < 64) issue_slice(sbB, s + 2, tid);

        if (kc == 1) {
            // epilogue for n-chunk nc: d = ||e||^2 - 2*dot, running best/second
            const int cb = nc * 128 + c0w + (lane & 3) * 2;
            float en[16];
            #pragma unroll
            for (int ni = 0; ni < 8; ++ni) {
                en[ni * 2]     = __ldg(g_enorm + cb + ni * 8);
                en[ni * 2 + 1] = __ldg(g_enorm + cb + ni * 8 + 1);
            }
            #pragma unroll
            for (int mi = 0; mi < 2; ++mi)
                #pragma unroll
                for (int hi = 0; hi < 2; ++hi) {
                    const int st = mi * 2 + hi;
                    #pragma unroll
                    for (int ni = 0; ni < 8; ++ni)
                        #pragma unroll
                        for (int p = 0; p < 2; ++p) {
                            float dd = fmaf(acc[mi][ni][hi * 2 + p], -2.0f, en[ni * 2 + p]);
                            int  idx = cb + ni * 8 + p;
                            float od = bd[st];
                            bd[st] = fminf(od, dd);
                            bi[st] = (dd < od) ? idx : bi[st];   // strict <: lowest idx on tie
                            b2[st] = fminf(b2[st], fmaxf(od, dd));
                        }
                }
        }
    }

    // ---- quad reduce (lanes sharing rows differ only in cols) ----
    #pragma unroll
    for (int off = 1; off <= 2; off <<= 1) {
        #pragma unroll
        for (int st = 0; st < 4; ++st) {
            float obd = __shfl_xor_sync(0xffffffffu, bd[st], off);
            float ob2 = __shfl_xor_sync(0xffffffffu, b2[st], off);
            int   obi = __shfl_xor_sync(0xffffffffu, bi[st], off);
            float nb2 = fminf(fminf(b2[st], ob2), fmaxf(bd[st], obd));
            if (obd < bd[st] || (obd == bd[st] && obi < bi[st])) { bd[st] = obd; bi[st] = obi; }
            b2[st] = nb2;
        }
    }

    __syncthreads();   // all cp.async retired (WAIT(0) above); reuse B space
    float* sd   = (float*)(smem_raw + SMEM_B_OFF);
    float* s2   = sd + 256;
    int*   si   = (int*)(s2 + 256);
    int*   idxf = si + 256;

    if ((lane & 3) == 0) {
        const int g = lane >> 2;
        #pragma unroll
        for (int st = 0; st < 4; ++st) {
            int row   = r0 + g + st * 8;
            int wslot = (wid >> 2) * 128 + row;
            sd[wslot] = bd[st]; s2[wslot] = b2[st]; si[wslot] = bi[st];
        }
    }
    __syncthreads();

    if (tid < 128) {
        float d1a = sd[tid], d1b = sd[128 + tid];
        float d2a = s2[tid], d2b = s2[128 + tid];
        int   ia  = si[tid], ib  = si[128 + tid];
        float D2 = fminf(fminf(d2a, d2b), fmaxf(d1a, d1b));
        float D1; int I1;
        if (d1b < d1a || (d1b == d1a && ib < ia)) { D1 = d1b; I1 = ib; }
        else                                      { D1 = d1a; I1 = ia; }
        int token = m0 + tid;
        if (outi_f) outi_f[token] = (float)I1;
        if (outi_i) outi_i[token] = I1;
        if (D2 - D1 < THRESH) {
            int p = atomicAdd(&g_flag_count, 1);
            g_flag_list[p] = token;
            g_best[token]  = 0xFFFFFFFFFFFFFFFFULL;
        }
        idxf[tid] = I1;
    }
    __syncthreads();

    if (outq) {
        const float4* emb4  = (const float4*)emb;
        float4*       outq4 = (float4*)outq;
        #pragma unroll 4
        for (int i = tid; i < 128 * 64; i += 256) {
            int row = i >> 6, c = i & 63;
            outq4[(size_t)(m0 + row) * 64 + c] = emb4[(size_t)idxf[row] * 64 + c];
        }
    }
}

// ---------------- rescue: exact fp32, code-parallel over flagged tokens ----------------
// 128 blocks x 32 codes each (e-rows in SMEM); flagged z rows batched 8/iter.
#define RC 32
#define RB 8
__global__ void __launch_bounds__(256, 1)
rescue_scan(const float* __restrict__ z, const float* __restrict__ emb)
{
    __shared__ float es[RC][D];   // 32KB
    __shared__ float zs[RB][D];   //  8KB
    __shared__ float ens[RC];
    const int n = g_flag_count;
    if (n == 0) return;
    const int lane = threadIdx.x & 31;
    const int w    = threadIdx.x >> 5;
    const int c0   = blockIdx.x * RC;

    for (int i = threadIdx.x; i < RC * 64; i += 256) {
        int r = i >> 6, c = i & 63;
        ((float4*)es[r])[c] = ((const float4*)(emb + (size_t)(c0 + r) * D))[c];
    }
    if (threadIdx.x < RC) ens[threadIdx.x] = g_enorm[c0 + threadIdx.x];

    for (int base = 0; base < n; base += RB) {
        int nb = min(RB, n - base);
        __syncthreads();
        for (int i = threadIdx.x; i < nb * 64; i += 256) {
            int ti = i >> 6, c = i & 63;
            ((float4*)zs[ti])[c] =
                ((const float4*)(z + (size_t)g_flag_list[base + ti] * D))[c];
        }
        __syncthreads();
        for (int ti = 0; ti < nb; ++ti) {
            float4 a = ((const float4*)zs[ti])[lane];
            float4 b = ((const float4*)zs[ti])[lane + 32];
            unsigned long long bestpk = 0xFFFFFFFFFFFFFFFFULL;
            #pragma unroll
            for (int q = 0; q < 4; ++q) {
                int code = w * 4 + q;                // 0..31 within block
                float4 x = ((const float4*)es[code])[lane];
                float4 y = ((const float4*)es[code])[lane + 32];
                float s = a.x*x.x + a.y*x.y + a.z*x.z + a.w*x.w
                        + b.x*y.x + b.y*y.y + b.z*y.z + b.w*y.w;
                #pragma unroll
                for (int off = 16; off; off >>= 1) s += __shfl_xor_sync(0xffffffffu, s, off);
                if (lane == 0) {
                    float d = fmaf(s, -2.0f, ens[code]);
                    unsigned int bits = __float_as_uint(d);
                    unsigned int key  = (bits & 0x80000000u) ? ~bits : (bits | 0x80000000u);
                    unsigned long long pk =
                        ((unsigned long long)key << 32) | (unsigned)(c0 + code);
                    if (pk < bestpk) bestpk = pk;    // lowest idx among equal keys
                }
            }
            if (lane == 0)
                atomicMin(&g_best[g_flag_list[base + ti]], bestpk);
        }
    }
}

__global__ void __launch_bounds__(256, 1)
rescue_fix(const float* __restrict__ emb, float* __restrict__ outq,
           float* __restrict__ outi_f, int* __restrict__ outi_i)
{
    const int n = g_flag_count;
    for (int fi = blockIdx.x; fi < n; fi += gridDim.x) {
        const int token = g_flag_list[fi];
        const int best  = (int)(g_best[token] & 0xFFFFFFFFu);
        if (threadIdx.x == 0) {
            if (outi_f) outi_f[token] = (float)best;
            if (outi_i) outi_i[token] = best;
        }
        if (outq) {
            for (int c = threadIdx.x; c < 64; c += 256)
                ((float4*)(outq + (size_t)token * D))[c] =
                    ((const float4*)(emb + (size_t)best * D))[c];
        }
    }
}

// ---------------- kernel_launch ----------------
extern "C" void kernel_launch(void* const* d_in, const int* in_sizes, int n_in,
                              void* d_out, int out_size)
{
    const float* z   = (const float*)d_in[0];
    const float* emb = (const float*)d_in[1];
    const int n_tokens = in_sizes[0] / D;   // 65536

    // Output layout defense: reference returns (z_quantized, indices).
    float* out    = (float*)d_out;
    float* outq   = nullptr;
    float* outi_f = nullptr;
    int*   outi_i = nullptr;
    const long long full = (long long)n_tokens * D;
    if ((long long)out_size >= full + n_tokens) { outq = out; outi_f = out + full; }
    else if ((long long)out_size >= full)       { outq = out; }
    else                                        { outi_i = (int*)d_out; }

    conv_z_kernel<<<(NTOK * D / 4 + 255) / 256, 256>>>(z);
    conv_e_kernel<<<(NCODE * D / 4 + 255) / 256, 256>>>(emb);
    enorm_kernel<<<NCODE / 8, 256>>>(emb);

    cudaFuncSetAttribute(vq_main, cudaFuncAttributeMaxDynamicSharedMemorySize, SMEM_TOTAL);
    vq_main<<<n_tokens / 128, 256, SMEM_TOTAL>>>(emb, outq, outi_f, outi_i);

    rescue_scan<<<NCODE / RC, 256>>>(z, emb);
    rescue_fix<<<128, 256>>>(emb, outq, outi_f, outi_i);
}

// round 17
// speedup vs baseline: 4.5294x; 1.7851x over previous
#include <cuda_runtime.h>
#include <cuda_fp16.h>
#include <cstdint>
#include <cstddef>
#include <cstring>

#define D       256
#define NTOK    65536
#define NCODE   4096
#define THRESH  0.12f

// A: [m][k] rows 256 fp16 padded to 264 (528B); B: 64-code slices, rows padded to 136 (272B)
#define A_STRIDE_B  528
#define B_STRIDE_B  272
#define SMEM_A_BYTES (128 * A_STRIDE_B)            // 67584
#define B_BUF_BYTES  (64 * B_STRIDE_B)             // 17408
#define SMEM_B_OFF   SMEM_A_BYTES
#define SMEM_TOTAL   (SMEM_A_BYTES + 2 * B_BUF_BYTES)  // 102400 -> 2 CTAs/SM

__device__ __align__(16) __half g_zc[(size_t)NTOK * D];    // fp16(z)  32MB
__device__ __align__(16) __half g_ec[(size_t)NCODE * D];   // fp16(e)   2MB
__device__ float g_enorm[NCODE];
__device__ int   g_flag_count;
__device__ int   g_flag_list[NTOK];
__device__ unsigned long long g_best[NTOK];   // packed (ordered_dist<<32)|code, flagged only

// ---------------- PTX helpers (base-ISA only) ----------------
__device__ __forceinline__ uint32_t smem_u32(const void* p) {
    uint32_t a;
    asm("{ .reg .u64 t; cvta.to.shared.u64 t, %1; cvt.u32.u64 %0, t; }" : "=r"(a) : "l"(p));
    return a;
}
__device__ __forceinline__ void cp_async16(uint32_t dst, const void* src) {
    asm volatile("cp.async.cg.shared.global [%0], [%1], 16;" :: "r"(dst), "l"(src));
}
#define CP_COMMIT() asm volatile("cp.async.commit_group;" ::: "memory")
#define CP_WAIT(n)  asm volatile("cp.async.wait_group %0;" :: "n"(n) : "memory")

#define LDSM4(r, addr) \
    asm volatile("ldmatrix.sync.aligned.m8n8.x4.shared.b16 {%0,%1,%2,%3}, [%4];" \
        : "=r"((r)[0]), "=r"((r)[1]), "=r"((r)[2]), "=r"((r)[3]) : "r"(addr))

__device__ __forceinline__ void mma16816(float* c, const uint32_t* a, uint32_t b0, uint32_t b1) {
    asm volatile("mma.sync.aligned.m16n8k16.row.col.f32.f16.f16.f32 "
        "{%0,%1,%2,%3}, {%4,%5,%6,%7}, {%8,%9}, {%0,%1,%2,%3};"
        : "+f"(c[0]), "+f"(c[1]), "+f"(c[2]), "+f"(c[3])
        : "r"(a[0]), "r"(a[1]), "r"(a[2]), "r"(a[3]), "r"(b0), "r"(b1));
}

// ---------------- prep kernels ----------------
__global__ void enorm_kernel(const float* __restrict__ e) {
    if (blockIdx.x == 0 && threadIdx.x == 0) g_flag_count = 0;
    int row  = blockIdx.x * 8 + (threadIdx.x >> 5);
    int lane = threadIdx.x & 31;
    if (row >= NCODE) return;
    const float4* e4 = (const float4*)(e + (size_t)row * D);
    float4 a = e4[lane], b = e4[lane + 32];
    float s = a.x*a.x + a.y*a.y + a.z*a.z + a.w*a.w
            + b.x*b.x + b.y*b.y + b.z*b.z + b.w*b.w;
    #pragma unroll
    for (int off = 16; off; off >>= 1) s += __shfl_xor_sync(0xffffffffu, s, off);
    if (lane == 0) g_enorm[row] = s;
}

// fp32 -> fp16 convert (hi only), writing the __device__ globals from DEVICE
// code. Dropped bits are O(2^-11) relative; distance noise sigma ~1.3e-2,
// guarded by THRESH=0.12 (~9 sigma) + exact-fp32 rescue.
__device__ __forceinline__ void conv4(const float4* src, __half* dst, int i) {
    float4 v = src[i];
    __half2 h0 = __floats2half2_rn(v.x, v.y);
    __half2 h1 = __floats2half2_rn(v.z, v.w);
    uint2 pk;
    memcpy(&pk.x, &h0, 4);
    memcpy(&pk.y, &h1, 4);
    ((uint2*)dst)[i] = pk;
}
__global__ void conv_z_kernel(const float* __restrict__ z) {
    int i = blockIdx.x * blockDim.x + threadIdx.x;
    if (i < NTOK * D / 4) conv4((const float4*)z, g_zc, i);
}
__global__ void conv_e_kernel(const float* __restrict__ e) {
    int i = blockIdx.x * blockDim.x + threadIdx.x;
    if (i < NCODE * D / 4) conv4((const float4*)e, g_ec, i);
}

// ---------------- main HMMA kernel ----------------
extern __shared__ __align__(1024) char smem_raw[];

// slice s: 64 codes x 128 K.  n0 = (s>>1)*64, k0 = (s&1)*128
__device__ __forceinline__ void issue_slice(uint32_t sbB, int s, int tid) {
    const int buf = s & 1;
    const int n0  = (s >> 1) * 64;
    const int k0  = (s & 1) * 128;
    #pragma unroll
    for (int it = 0; it < 4; ++it) {
        int i  = it * 256 + tid;            // 0..1023
        int n  = i >> 4;
        int kc = i & 15;
        cp_async16(sbB + buf * B_BUF_BYTES + n * B_STRIDE_B + kc * 16,
                   g_ec + (size_t)(n0 + n) * D + k0 + kc * 8);
    }
    CP_COMMIT();
}

__global__ void __launch_bounds__(256, 2)
vq_main(const float* __restrict__ emb, float* __restrict__ outq,
        float* __restrict__ outi_f, int* __restrict__ outi_i)
{
    const int tid  = threadIdx.x;
    const int wid  = tid >> 5;
    const int lane = tid & 31;
    const int m0   = blockIdx.x * 128;
    const uint32_t sbA = smem_u32(smem_raw);
    const uint32_t sbB = sbA + SMEM_B_OFF;

    const int r0  = (wid & 3) * 32;     // warp_m: 32 token rows
    const int c0w = (wid >> 2) * 32;    // warp_n: 32 code cols

    // ldmatrix lane addressing: j selects which 8x8, rr its row, kk its k-half
    const int j  = lane >> 3;
    const int rr = ((j & 1) * 8 + (lane & 7));
    const int kk = (j >> 1) * 8;

    // ---- stage A (128 x 256 fp16) ----
    #pragma unroll
    for (int it = 0; it < 16; ++it) {
        int i  = it * 256 + tid;            // 0..4095
        int m  = i >> 5;
        int kc = i & 31;
        cp_async16(sbA + m * A_STRIDE_B + kc * 16,
                   g_zc + (size_t)(m0 + m) * D + kc * 8);
    }
    CP_COMMIT();
    issue_slice(sbB, 0, tid);
    issue_slice(sbB, 1, tid);

    float acc[2][4][4];
    float bd[4], b2[4];
    int   bi[4];
    #pragma unroll
    for (int s = 0; s < 4; ++s) { bd[s] = 3.402823466e38f; b2[s] = 3.402823466e38f; bi[s] = 0; }

    for (int s = 0; s < 128; ++s) {
        const int kc = s & 1;
        const int nc = s >> 1;
        // last slices: nothing further outstanding, so drain fully.
        if (s >= 126) { CP_WAIT(0); } else { CP_WAIT(1); }
        __syncthreads();

        if (kc == 0) {
            #pragma unroll
            for (int mi = 0; mi < 2; ++mi)
                #pragma unroll
                for (int ni = 0; ni < 4; ++ni)
                    #pragma unroll
                    for (int q = 0; q < 4; ++q) acc[mi][ni][q] = 0.0f;
        }

        const uint32_t aB = sbA + (r0 + rr) * A_STRIDE_B + (kc * 128 + kk) * 2;
        const uint32_t bB = sbB + (s & 1) * B_BUF_BYTES + (c0w + rr) * B_STRIDE_B + kk * 2;

        #pragma unroll
        for (int ks = 0; ks < 8; ++ks) {
            uint32_t a[2][4];
            #pragma unroll
            for (int mi = 0; mi < 2; ++mi)
                LDSM4(a[mi], aB + mi * 16 * A_STRIDE_B + ks * 32);
            #pragma unroll
            for (int nq = 0; nq < 2; ++nq) {
                uint32_t b[4];
                LDSM4(b, bB + nq * 16 * B_STRIDE_B + ks * 32);
                #pragma unroll
                for (int mi = 0; mi < 2; ++mi) {
                    mma16816(acc[mi][nq * 2],     a[mi], b[0], b[2]);
                    mma16816(acc[mi][nq * 2 + 1], a[mi], b[1], b[3]);
                }
            }
        }
        __syncthreads();
        if (s + 2 < 128) issue_slice(sbB, s + 2, tid);

        if (kc == 1) {
            // epilogue for n-chunk nc (64 codes): d = ||e||^2 - 2*dot
            const int cb = nc * 64 + c0w + (lane & 3) * 2;
            float en[8];
            #pragma unroll
            for (int ni = 0; ni < 4; ++ni) {
                en[ni * 2]     = __ldg(g_enorm + cb + ni * 8);
                en[ni * 2 + 1] = __ldg(g_enorm + cb + ni * 8 + 1);
            }
            #pragma unroll
            for (int mi = 0; mi < 2; ++mi)
                #pragma unroll
                for (int hi = 0; hi < 2; ++hi) {
                    const int st = mi * 2 + hi;
                    #pragma unroll
                    for (int ni = 0; ni < 4; ++ni)
                        #pragma unroll
                        for (int p = 0; p < 2; ++p) {
                            float dd = fmaf(acc[mi][ni][hi * 2 + p], -2.0f, en[ni * 2 + p]);
                            int  idx = cb + ni * 8 + p;
                            float od = bd[st];
                            bd[st] = fminf(od, dd);
                            bi[st] = (dd < od) ? idx : bi[st];   // strict <: lowest idx on tie
                            b2[st] = fminf(b2[st], fmaxf(od, dd));
                        }
                }
        }
    }

    // ---- quad reduce (lanes sharing rows differ only in cols) ----
    #pragma unroll
    for (int off = 1; off <= 2; off <<= 1) {
        #pragma unroll
        for (int st = 0; st < 4; ++st) {
            float obd = __shfl_xor_sync(0xffffffffu, bd[st], off);
            float ob2 = __shfl_xor_sync(0xffffffffu, b2[st], off);
            int   obi = __shfl_xor_sync(0xffffffffu, bi[st], off);
            float nb2 = fminf(fminf(b2[st], ob2), fmaxf(bd[st], obd));
            if (obd < bd[st] || (obd == bd[st] && obi < bi[st])) { bd[st] = obd; bi[st] = obi; }
            b2[st] = nb2;
        }
    }

    __syncthreads();   // all cp.async retired (WAIT(0) above); reuse B space
    float* sd   = (float*)(smem_raw + SMEM_B_OFF);
    float* s2   = sd + 256;
    int*   si   = (int*)(s2 + 256);
    int*   idxf = si + 256;

    if ((lane & 3) == 0) {
        const int g = lane >> 2;
        #pragma unroll
        for (int st = 0; st < 4; ++st) {
            int row   = r0 + g + st * 8;
            int wslot = (wid >> 2) * 128 + row;
            sd[wslot] = bd[st]; s2[wslot] = b2[st]; si[wslot] = bi[st];
        }
    }
    __syncthreads();

    if (tid < 128) {
        float d1a = sd[tid], d1b = sd[128 + tid];
        float d2a = s2[tid], d2b = s2[128 + tid];
        int   ia  = si[tid], ib  = si[128 + tid];
        float D2 = fminf(fminf(d2a, d2b), fmaxf(d1a, d1b));
        float D1; int I1;
        if (d1b < d1a || (d1b == d1a && ib < ia)) { D1 = d1b; I1 = ib; }
        else                                      { D1 = d1a; I1 = ia; }
        int token = m0 + tid;
        if (outi_f) outi_f[token] = (float)I1;
        if (outi_i) outi_i[token] = I1;
        if (D2 - D1 < THRESH) {
            int p = atomicAdd(&g_flag_count, 1);
            g_flag_list[p] = token;
            g_best[token]  = 0xFFFFFFFFFFFFFFFFULL;
        }
        idxf[tid] = I1;
    }
    __syncthreads();

    if (outq) {
        const float4* emb4  = (const float4*)emb;
        float4*       outq4 = (float4*)outq;
        #pragma unroll 4
        for (int i = tid; i < 128 * 64; i += 256) {
            int row = i >> 6, c = i & 63;
            outq4[(size_t)(m0 + row) * 64 + c] = emb4[(size_t)idxf[row] * 64 + c];
        }
    }
}

// ---------------- rescue: exact fp32, thread-parallel (no shfl chains in k-loop) ----
// 128 blocks x 32 codes; es staged TRANSPOSED [k4][code] so each thread owns
// (token, code) pairs and accumulates privately; one 64b shfl argmin per token.
#define RC 32
#define RB 16
__global__ void __launch_bounds__(256, 1)
rescue_scan(const float* __restrict__ z, const float* __restrict__ emb)
{
    __shared__ float4 es4[64][RC];   // [k4][code]  32KB
    __shared__ float4 zs4[RB][64];   // [token][k4] 16KB
    __shared__ float  ens[RC];
    const int n = g_flag_count;
    if (n == 0) return;
    const int tid  = threadIdx.x;
    const int lane = tid & 31;
    const int w    = tid >> 5;
    const int c0   = blockIdx.x * RC;

    for (int i = tid; i < RC * 64; i += 256) {
        int r = i >> 6, k4 = i & 63;
        es4[k4][r] = ((const float4*)(emb + (size_t)(c0 + r) * D))[k4];
    }
    if (tid < RC) ens[tid] = g_enorm[c0 + tid];

    for (int base = 0; base < n; base += RB) {
        int nb = min(RB, n - base);
        __syncthreads();
        for (int i = tid; i < nb * 64; i += 256) {
            int ti = i >> 6, c = i & 63;
            zs4[ti][c] = ((const float4*)(z + (size_t)g_flag_list[base + ti] * D))[c];
        }
        __syncthreads();
        // warp w handles tokens {w, w+8}; lane = code
        float a0 = 0.0f, a1 = 0.0f;
        #pragma unroll 4
        for (int k4 = 0; k4 < 64; ++k4) {
            float4 e = es4[k4][lane];
            float4 x = zs4[w][k4];
            float4 y = zs4[w + 8][k4];
            a0 = fmaf(x.x, e.x, fmaf(x.y, e.y, fmaf(x.z, e.z, fmaf(x.w, e.w, a0))));
            a1 = fmaf(y.x, e.x, fmaf(y.y, e.y, fmaf(y.z, e.z, fmaf(y.w, e.w, a1))));
        }
        #pragma unroll
        for (int h = 0; h < 2; ++h) {
            int   t   = h ? (w + 8) : w;
            float acc = h ? a1 : a0;
            if (t < nb) {
                float d = fmaf(acc, -2.0f, ens[lane]);
                unsigned int bits = __float_as_uint(d);
                unsigned int key  = (bits & 0x80000000u) ? ~bits : (bits | 0x80000000u);
                unsigned long long pk =
                    ((unsigned long long)key << 32) | (unsigned)(c0 + lane);
                #pragma unroll
                for (int off = 16; off; off >>= 1) {
                    unsigned long long o = __shfl_xor_sync(0xffffffffu, pk, off);
                    if (o < pk) pk = o;    // lowest code wins among equal keys
                }
                if (lane == 0)
                    atomicMin(&g_best[g_flag_list[base + t]], pk);
            }
        }
    }
}

__global__ void __launch_bounds__(256, 1)
rescue_fix(const float* __restrict__ emb, float* __restrict__ outq,
           float* __restrict__ outi_f, int* __restrict__ outi_i)
{
    const int n = g_flag_count;
    for (int fi = blockIdx.x; fi < n; fi += gridDim.x) {
        const int token = g_flag_list[fi];
        const int best  = (int)(g_best[token] & 0xFFFFFFFFu);
        if (threadIdx.x == 0) {
            if (outi_f) outi_f[token] = (float)best;
            if (outi_i) outi_i[token] = best;
        }
        if (outq) {
            for (int c = threadIdx.x; c < 64; c += 256)
                ((float4*)(outq + (size_t)token * D))[c] =
                    ((const float4*)(emb + (size_t)best * D))[c];
        }
    }
}

// ---------------- kernel_launch ----------------
extern "C" void kernel_launch(void* const* d_in, const int* in_sizes, int n_in,
                              void* d_out, int out_size)
{
    const float* z   = (const float*)d_in[0];
    const float* emb = (const float*)d_in[1];
    const int n_tokens = in_sizes[0] / D;   // 65536

    // Output layout defense: reference returns (z_quantized, indices).
    float* out    = (float*)d_out;
    float* outq   = nullptr;
    float* outi_f = nullptr;
    int*   outi_i = nullptr;
    const long long full = (long long)n_tokens * D;
    if ((long long)out_size >= full + n_tokens) { outq = out; outi_f = out + full; }
    else if ((long long)out_size >= full)       { outq = out; }
    else                                        { outi_i = (int*)d_out; }

    conv_z_kernel<<<(NTOK * D / 4 + 255) / 256, 256>>>(z);
    conv_e_kernel<<<(NCODE * D / 4 + 255) / 256, 256>>>(emb);
    enorm_kernel<<<NCODE / 8, 256>>>(emb);

    cudaFuncSetAttribute(vq_main, cudaFuncAttributeMaxDynamicSharedMemorySize, SMEM_TOTAL);
    vq_main<<<n_tokens / 128, 256, SMEM_TOTAL>>>(emb, outq, outi_f, outi_i);

    rescue_scan<<<NCODE / RC, 256>>>(z, emb);
    rescue_fix<<<128, 256>>>(emb, outq, outi_f, outi_i);
}